// round 2
// baseline (speedup 1.0000x reference)
#include <cuda_runtime.h>
#include <math.h>

#define NP 8388608          // 32*512*512 pixels
#define HW 262144           // 512*512
#define BSTRIDE 786432      // 3*HW
#define BETA_F 0.15f

// ---------------- device scratch (allocation-free: __device__ globals) ----------------
__device__ double   g_acc[10];            // cnt, s0..2, p00,p01,p02,p11,p12,p22
__device__ double   g_emid[3], g_elarge[3];
__device__ float    g_emidf[3], g_elargef[3];
__device__ unsigned g_pfx[2];
__device__ long long g_rank[2];
__device__ unsigned g_phicount;
__device__ float    g_M[6];               // 2x3 row-major (HE^T HE)^-1 HE^T
__device__ float    g_s[2];               // MAXCREF / maxC
__device__ unsigned g_hist[2][256];
__device__ unsigned g_keysA[NP];          // phi keys, then C0 keys
__device__ unsigned g_keysB[NP];          // C1 keys

// ---------------- helpers ----------------
__device__ __forceinline__ unsigned f2k(float f) {
    unsigned u = __float_as_uint(f);
    return u ^ (unsigned)(((int)u >> 31) | 0x80000000);
}
__device__ __forceinline__ float k2f(unsigned k) {
    unsigned u = (k & 0x80000000u) ? (k ^ 0x80000000u) : ~k;
    return __uint_as_float(u);
}
__device__ __forceinline__ void load_od(const float* __restrict__ x, int t, float od[3]) {
    int b = t >> 18, hw = t & (HW - 1);
    const float* p = x + (size_t)b * BSTRIDE + hw;
    od[0] = -logf((p[0]        + 1.0f) / 240.0f);
    od[1] = -logf((p[HW]       + 1.0f) / 240.0f);
    od[2] = -logf((p[2 * HW]   + 1.0f) / 240.0f);
}

// ---------------- init ----------------
__global__ void k_init() {
    int i = threadIdx.x;
    if (i < 10) g_acc[i] = 0.0;
    if (i == 0) g_phicount = 0u;
    for (int j = i; j < 512; j += blockDim.x) ((unsigned*)g_hist)[j] = 0u;
}

// ---------------- pass 1: masked moments ----------------
__global__ void k_stats(const float* __restrict__ x) {
    double a[10];
#pragma unroll
    for (int i = 0; i < 10; i++) a[i] = 0.0;
    for (int t = blockIdx.x * blockDim.x + threadIdx.x; t < NP; t += gridDim.x * blockDim.x) {
        float od[3]; load_od(x, t, od);
        bool keep = !(od[0] < BETA_F || od[1] < BETA_F || od[2] < BETA_F);
        if (keep) {
            double d0 = od[0], d1 = od[1], d2 = od[2];
            a[0] += 1.0; a[1] += d0; a[2] += d1; a[3] += d2;
            a[4] += d0 * d0; a[5] += d0 * d1; a[6] += d0 * d2;
            a[7] += d1 * d1; a[8] += d1 * d2; a[9] += d2 * d2;
        }
    }
#pragma unroll
    for (int o = 16; o; o >>= 1)
#pragma unroll
        for (int i = 0; i < 10; i++) a[i] += __shfl_down_sync(0xffffffffu, a[i], o);
    __shared__ double sh[8][10];
    int lane = threadIdx.x & 31, w = threadIdx.x >> 5;
    if (lane == 0)
        for (int i = 0; i < 10; i++) sh[w][i] = a[i];
    __syncthreads();
    if (threadIdx.x == 0) {
        for (int ww = 1; ww < (int)(blockDim.x >> 5); ww++)
            for (int i = 0; i < 10; i++) sh[0][i] += sh[ww][i];
        for (int i = 0; i < 10; i++) atomicAdd(&g_acc[i], sh[0][i]);
    }
}

// ---------------- 3x3 symmetric Jacobi eigensolver (double) ----------------
__device__ void eig3(double A[3][3], double V[3][3], double w[3]) {
    for (int i = 0; i < 3; i++)
        for (int j = 0; j < 3; j++) V[i][j] = (i == j) ? 1.0 : 0.0;
    const int PQ[3][2] = {{0, 1}, {0, 2}, {1, 2}};
    for (int sweep = 0; sweep < 64; sweep++) {
        double off = A[0][1] * A[0][1] + A[0][2] * A[0][2] + A[1][2] * A[1][2];
        if (off < 1e-300) break;
        for (int r = 0; r < 3; r++) {
            int p = PQ[r][0], q = PQ[r][1];
            double apq = A[p][q];
            if (fabs(apq) < 1e-300) continue;
            double theta = (A[q][q] - A[p][p]) / (2.0 * apq);
            double tt = (theta >= 0.0 ? 1.0 : -1.0) / (fabs(theta) + sqrt(theta * theta + 1.0));
            double c = 1.0 / sqrt(tt * tt + 1.0);
            double s = tt * c;
            double app = A[p][p], aqq = A[q][q];
            A[p][p] = app - tt * apq;
            A[q][q] = aqq + tt * apq;
            A[p][q] = A[q][p] = 0.0;
            int k = 3 - p - q;
            double akp = A[k][p], akq = A[k][q];
            A[k][p] = A[p][k] = c * akp - s * akq;
            A[k][q] = A[q][k] = s * akp + c * akq;
            for (int k2 = 0; k2 < 3; k2++) {
                double vp = V[k2][p], vq = V[k2][q];
                V[k2][p] = c * vp - s * vq;
                V[k2][q] = s * vp + c * vq;
            }
        }
    }
    for (int i = 0; i < 3; i++) w[i] = A[i][i];
    // sort ascending (bubble), swap eigenvector columns along
    for (int pass = 0; pass < 2; pass++)
        for (int i = 0; i < 2; i++)
            if (w[i] > w[i + 1]) {
                double tw = w[i]; w[i] = w[i + 1]; w[i + 1] = tw;
                for (int k = 0; k < 3; k++) {
                    double tv = V[k][i]; V[k][i] = V[k][i + 1]; V[k][i + 1] = tv;
                }
            }
}

// ---------------- finalize stats -> eigvecs, phi ranks ----------------
__global__ void k_finalize1() {
    double n = g_acc[0];
    double mu0 = g_acc[1] / n, mu1 = g_acc[2] / n, mu2 = g_acc[3] / n;
    double inv = 1.0 / (n - 1.0);
    double A[3][3];
    A[0][0] = (g_acc[4] - n * mu0 * mu0) * inv;
    A[0][1] = A[1][0] = (g_acc[5] - n * mu0 * mu1) * inv;
    A[0][2] = A[2][0] = (g_acc[6] - n * mu0 * mu2) * inv;
    A[1][1] = (g_acc[7] - n * mu1 * mu1) * inv;
    A[1][2] = A[2][1] = (g_acc[8] - n * mu1 * mu2) * inv;
    A[2][2] = (g_acc[9] - n * mu2 * mu2) * inv;
    double V[3][3], w[3];
    eig3(A, V, w);
    for (int i = 0; i < 3; i++) {
        g_emid[i] = V[i][1];  g_elarge[i] = V[i][2];
        g_emidf[i] = (float)V[i][1]; g_elargef[i] = (float)V[i][2];
    }
    double nm1 = n - 1.0;
    g_rank[0] = llrint((0.01 * 1.0) * nm1);    // minPhi index (0-based)
    g_rank[1] = llrint((0.01 * 99.0) * nm1);   // maxPhi index
    g_pfx[0] = 0u; g_pfx[1] = 0u;
}

// ---------------- pass 2: phi of masked pixels, compacted ----------------
__global__ void k_phi(const float* __restrict__ x) {
    float e10 = g_emidf[0], e11 = g_emidf[1], e12 = g_emidf[2];
    float e20 = g_elargef[0], e21 = g_elargef[1], e22 = g_elargef[2];
    int lane = threadIdx.x & 31;
    for (int t = blockIdx.x * blockDim.x + threadIdx.x; t < NP; t += gridDim.x * blockDim.x) {
        float od[3]; load_od(x, t, od);
        bool keep = !(od[0] < BETA_F || od[1] < BETA_F || od[2] < BETA_F);
        unsigned key = 0u;
        if (keep) {
            float t1 = fmaf(od[2], e12, fmaf(od[1], e11, od[0] * e10));
            float t2 = fmaf(od[2], e22, fmaf(od[1], e21, od[0] * e20));
            key = f2k(atan2f(t2, t1));
        }
        unsigned m = __ballot_sync(0xffffffffu, keep);
        if (m) {
            int leader = __ffs(m) - 1;
            unsigned base = 0u;
            if (lane == leader) base = atomicAdd(&g_phicount, (unsigned)__popc(m));
            base = __shfl_sync(0xffffffffu, base, leader);
            if (keep) {
                int off = __popc(m & ((1u << lane) - 1u));
                g_keysA[base + off] = key;
            }
        }
    }
}

// ---------------- radix-select histogram pass ----------------
__global__ void k_hist(int shift, int phase) {
    __shared__ unsigned sh[2][256];
    for (int i = threadIdx.x; i < 512; i += blockDim.x) ((unsigned*)sh)[i] = 0u;
    __syncthreads();
    unsigned n = phase ? (unsigned)NP : g_phicount;
    const unsigned* __restrict__ A = g_keysA;
    const unsigned* __restrict__ B = phase ? g_keysB : g_keysA;
    unsigned p0 = g_pfx[0], p1 = g_pfx[1];
    for (unsigned t = blockIdx.x * blockDim.x + threadIdx.x; t < n; t += gridDim.x * blockDim.x) {
        unsigned ka = A[t];
        if (shift == 24 || (ka >> (shift + 8)) == p0) atomicAdd(&sh[0][(ka >> shift) & 255u], 1u);
        unsigned kb = B[t];
        if (shift == 24 || (kb >> (shift + 8)) == p1) atomicAdd(&sh[1][(kb >> shift) & 255u], 1u);
    }
    __syncthreads();
    for (int i = threadIdx.x; i < 256; i += blockDim.x) {
        if (sh[0][i]) atomicAdd(&g_hist[0][i], sh[0][i]);
        if (sh[1][i]) atomicAdd(&g_hist[1][i], sh[1][i]);
    }
}

// ---------------- radix-select rank refine (one warp per target) ----------------
__global__ void k_select() {
    int tsel = threadIdx.x >> 5;
    int lane = threadIdx.x & 31;
    if (tsel > 1) return;
    long long r = g_rank[tsel];
    unsigned run = 0u; int found = -1; unsigned before = 0u;
    for (int base = 0; base < 256; base += 32) {
        unsigned c = g_hist[tsel][base + lane];
        unsigned inc = c;
#pragma unroll
        for (int o = 1; o < 32; o <<= 1) {
            unsigned v = __shfl_up_sync(0xffffffffu, inc, o);
            if (lane >= o) inc += v;
        }
        unsigned tot = __shfl_sync(0xffffffffu, inc, 31);
        if (found < 0) {
            long long excl = (long long)run + (long long)(inc - c);
            long long cum  = (long long)run + (long long)inc;
            bool hit = (excl <= r) && (cum > r);
            unsigned hm = __ballot_sync(0xffffffffu, hit);
            if (hm) {
                int hl = __ffs(hm) - 1;
                found = base + hl;
                before = run + __shfl_sync(0xffffffffu, inc - c, hl);
            }
        }
        run += tot;
        g_hist[tsel][base + lane] = 0u;   // zero for next pass
    }
    if (lane == 0) {
        g_pfx[tsel] = (g_pfx[tsel] << 8) | (unsigned)found;
        g_rank[tsel] = r - (long long)before;
    }
}

// ---------------- finalize phi -> HE -> M, set Cmat ranks ----------------
__global__ void k_finalize2() {
    double minPhi = (double)k2f(g_pfx[0]);
    double maxPhi = (double)k2f(g_pfx[1]);
    double vMin[3], vMax[3];
    double cmin = cos(minPhi), smin = sin(minPhi);
    double cmax = cos(maxPhi), smax = sin(maxPhi);
    for (int i = 0; i < 3; i++) {
        vMin[i] = cmin * g_emid[i] + smin * g_elarge[i];
        vMax[i] = cmax * g_emid[i] + smax * g_elarge[i];
    }
    double h1[3], h2[3];
    if (vMin[0] > vMax[0]) {
        for (int i = 0; i < 3; i++) { h1[i] = vMin[i]; h2[i] = vMax[i]; }
    } else {
        for (int i = 0; i < 3; i++) { h1[i] = vMax[i]; h2[i] = vMin[i]; }
    }
    double a = h1[0]*h1[0] + h1[1]*h1[1] + h1[2]*h1[2];
    double b = h1[0]*h2[0] + h1[1]*h2[1] + h1[2]*h2[2];
    double d = h2[0]*h2[0] + h2[1]*h2[1] + h2[2]*h2[2];
    double det = a * d - b * b;
    for (int i = 0; i < 3; i++) {
        g_M[i]     = (float)((d * h1[i] - b * h2[i]) / det);
        g_M[3 + i] = (float)((a * h2[i] - b * h1[i]) / det);
    }
    double nm1 = (double)(NP - 1);
    long long r99 = llrint((0.01 * 99.0) * nm1);
    g_rank[0] = r99; g_rank[1] = r99;
    g_pfx[0] = 0u; g_pfx[1] = 0u;
}

// ---------------- pass 3: Cmat keys for all pixels ----------------
__global__ void k_cmat(const float* __restrict__ x) {
    float m0 = g_M[0], m1 = g_M[1], m2 = g_M[2];
    float m3 = g_M[3], m4 = g_M[4], m5 = g_M[5];
    for (int t = blockIdx.x * blockDim.x + threadIdx.x; t < NP; t += gridDim.x * blockDim.x) {
        float od[3]; load_od(x, t, od);
        float c0 = fmaf(od[2], m2, fmaf(od[1], m1, od[0] * m0));
        float c1 = fmaf(od[2], m5, fmaf(od[1], m4, od[0] * m3));
        g_keysA[t] = f2k(c0);
        g_keysB[t] = f2k(c1);
    }
}

// ---------------- finalize maxC -> scales ----------------
__global__ void k_finalize3() {
    float maxC0 = k2f(g_pfx[0]);
    float maxC1 = k2f(g_pfx[1]);
    g_s[0] = 1.9705f / maxC0;
    g_s[1] = 1.0308f / maxC1;
}

// ---------------- pass 4: normalized output ----------------
__global__ void k_out(const float* __restrict__ x, float* __restrict__ out) {
    float m0 = g_M[0], m1 = g_M[1], m2 = g_M[2];
    float m3 = g_M[3], m4 = g_M[4], m5 = g_M[5];
    float s0 = g_s[0], s1 = g_s[1];
    for (int t = blockIdx.x * blockDim.x + threadIdx.x; t < NP; t += gridDim.x * blockDim.x) {
        float od[3]; load_od(x, t, od);
        float c0 = fmaf(od[2], m2, fmaf(od[1], m1, od[0] * m0)) * s0;
        float c1 = fmaf(od[2], m5, fmaf(od[1], m4, od[0] * m3)) * s1;
        int b = t >> 18, hw = t & (HW - 1);
        float* o = out + (size_t)b * BSTRIDE + hw;
        o[0]      = fminf(240.0f * expf(-(fmaf(0.5626f, c0, 0.2159f * c1))), 255.0f);
        o[HW]     = fminf(240.0f * expf(-(fmaf(0.7201f, c0, 0.8012f * c1))), 255.0f);
        o[2 * HW] = fminf(240.0f * expf(-(fmaf(0.4062f, c0, 0.5581f * c1))), 255.0f);
    }
}

// ---------------- launch ----------------
extern "C" void kernel_launch(void* const* d_in, const int* in_sizes, int n_in,
                              void* d_out, int out_size) {
    const float* x = (const float*)d_in[0];
    float* out = (float*)d_out;
    const int TB = 256;
    const int GB_BIG = 2048;   // 2048*256 = 524288 threads -> 16 px/thread (exact)
    const int GB_SEL = 1024;

    k_init<<<1, 64>>>();
    k_stats<<<GB_BIG, TB>>>(x);
    k_finalize1<<<1, 1>>>();
    k_phi<<<GB_BIG, TB>>>(x);
    for (int p = 0; p < 4; p++) {
        k_hist<<<GB_SEL, TB>>>(24 - 8 * p, 0);
        k_select<<<1, 64>>>();
    }
    k_finalize2<<<1, 1>>>();
    k_cmat<<<GB_BIG, TB>>>(x);
    for (int p = 0; p < 4; p++) {
        k_hist<<<GB_SEL, TB>>>(24 - 8 * p, 1);
        k_select<<<1, 64>>>();
    }
    k_finalize3<<<1, 1>>>();
    k_out<<<GB_BIG, TB>>>(x, out);
}

// round 4
// speedup vs baseline: 1.8597x; 1.8597x over previous
#include <cuda_runtime.h>
#include <math.h>

#define NP 8388608          // 32*512*512 pixels
#define HW 262144           // 512*512
#define BSTRIDE 786432      // 3*HW
#define BETA_F 0.15f

// ---------------- device scratch (allocation-free: __device__ globals) ----------------
__device__ double   g_acc[10];             // cnt, s0..2, p00,p01,p02,p11,p12,p22
__device__ double   g_emid[3], g_elarge[3];
__device__ float    g_emidf[3], g_elargef[3];
__device__ unsigned g_pfx[2];
__device__ long long g_rank[2];
__device__ float    g_M[6];                // 2x3 row-major (HE^T HE)^-1 HE^T
__device__ float    g_s[2];                // MAXCREF / maxC
__device__ unsigned g_hist[2][256];
__device__ float    g_od[3ull * NP];       // OD cache, 3 planes (96 MB)
__device__ unsigned g_keysA[NP];
__device__ unsigned g_keysB[NP];

// ---------------- helpers ----------------
__device__ __forceinline__ unsigned f2k(float f) {
    unsigned u = __float_as_uint(f);
    return u ^ (unsigned)(((int)u >> 31) | 0x80000000);
}
__device__ __forceinline__ float k2f(unsigned k) {
    unsigned u = (k & 0x80000000u) ? (k ^ 0x80000000u) : ~k;
    return __uint_as_float(u);
}

// FFMA-only exp(y). Cody-Waite reduction + degree-7 Taylor. |rel err| < 1e-6.
__device__ __forceinline__ float fexp(float y) {
    float z = y * 1.4426950408889634f;       // y / ln2
    float n = rintf(z);
    float g = fmaf(n, -0.69314575f, y);      // Cody-Waite hi
    g = fmaf(n, -1.4286068e-6f, g);          // Cody-Waite lo ; g in [-0.3466, 0.3466]
    float r = 1.9841270e-4f;                 // 1/5040
    r = fmaf(r, g, 1.3888889e-3f);           // 1/720
    r = fmaf(r, g, 8.3333333e-3f);           // 1/120
    r = fmaf(r, g, 4.1666667e-2f);           // 1/24
    r = fmaf(r, g, 1.6666667e-1f);           // 1/6
    r = fmaf(r, g, 0.5f);                    // 1/2
    r = fmaf(r, g, 1.0f);                    // c1
    r = fmaf(r, g, 1.0f);                    // c0  (this line was missing before)
    int ni = (int)n;
    ni = ni < -126 ? -126 : (ni > 127 ? 127 : ni);
    float s = __int_as_float((unsigned)(ni + 127) << 23);
    return r * s;
}

// warp-aggregated shared-hist add
__device__ __forceinline__ void hadd(unsigned* row, unsigned digit, bool pred) {
    unsigned mm = __ballot_sync(0xffffffffu, pred);
    if (pred) {
        unsigned peers = __match_any_sync(mm, digit);
        int lane = threadIdx.x & 31;
        int leader = __ffs(peers) - 1;
        if (lane == leader) atomicAdd(&row[digit], (unsigned)__popc(peers));
    }
}

// ---------------- init ----------------
__global__ void k_init() {
    int i = threadIdx.x;
    if (i < 10) g_acc[i] = 0.0;
    for (int j = i; j < 512; j += blockDim.x) ((unsigned*)g_hist)[j] = 0u;
}

// ---------------- pass 1: OD cache + masked moments (float partials, dbl reduce) ----
__global__ void k_stats(const float* __restrict__ x) {
    float a[10];
#pragma unroll
    for (int i = 0; i < 10; i++) a[i] = 0.0f;
    int tid = blockIdx.x * blockDim.x + threadIdx.x;
    int stride = gridDim.x * blockDim.x;
    for (int q = tid; q < NP / 4; q += stride) {
        int t = q << 2;
        int b = t >> 18, hw = t & (HW - 1);
        const float* p = x + (size_t)b * BSTRIDE + hw;
        float4 v0 = *(const float4*)(p);
        float4 v1 = *(const float4*)(p + HW);
        float4 v2 = *(const float4*)(p + 2 * HW);
        float o0[4], o1[4], o2[4];
        o0[0] = -logf((v0.x + 1.0f) / 240.0f); o0[1] = -logf((v0.y + 1.0f) / 240.0f);
        o0[2] = -logf((v0.z + 1.0f) / 240.0f); o0[3] = -logf((v0.w + 1.0f) / 240.0f);
        o1[0] = -logf((v1.x + 1.0f) / 240.0f); o1[1] = -logf((v1.y + 1.0f) / 240.0f);
        o1[2] = -logf((v1.z + 1.0f) / 240.0f); o1[3] = -logf((v1.w + 1.0f) / 240.0f);
        o2[0] = -logf((v2.x + 1.0f) / 240.0f); o2[1] = -logf((v2.y + 1.0f) / 240.0f);
        o2[2] = -logf((v2.z + 1.0f) / 240.0f); o2[3] = -logf((v2.w + 1.0f) / 240.0f);
        *(float4*)(g_od + t)          = make_float4(o0[0], o0[1], o0[2], o0[3]);
        *(float4*)(g_od + NP + t)     = make_float4(o1[0], o1[1], o1[2], o1[3]);
        *(float4*)(g_od + 2 * NP + t) = make_float4(o2[0], o2[1], o2[2], o2[3]);
#pragma unroll
        for (int j = 0; j < 4; j++) {
            float d0 = o0[j], d1 = o1[j], d2 = o2[j];
            bool keep = !(d0 < BETA_F || d1 < BETA_F || d2 < BETA_F);
            if (keep) {
                a[0] += 1.0f; a[1] += d0; a[2] += d1; a[3] += d2;
                a[4] += d0 * d0; a[5] += d0 * d1; a[6] += d0 * d2;
                a[7] += d1 * d1; a[8] += d1 * d2; a[9] += d2 * d2;
            }
        }
    }
    double d[10];
#pragma unroll
    for (int i = 0; i < 10; i++) d[i] = (double)a[i];
#pragma unroll
    for (int o = 16; o; o >>= 1)
#pragma unroll
        for (int i = 0; i < 10; i++) d[i] += __shfl_down_sync(0xffffffffu, d[i], o);
    __shared__ double sh[8][10];
    int lane = threadIdx.x & 31, w = threadIdx.x >> 5;
    if (lane == 0)
        for (int i = 0; i < 10; i++) sh[w][i] = d[i];
    __syncthreads();
    if (threadIdx.x == 0) {
        for (int ww = 1; ww < (int)(blockDim.x >> 5); ww++)
            for (int i = 0; i < 10; i++) sh[0][i] += sh[ww][i];
        for (int i = 0; i < 10; i++) atomicAdd(&g_acc[i], sh[0][i]);
    }
}

// ---------------- 3x3 symmetric Jacobi eigensolver (double) ----------------
__device__ void eig3(double A[3][3], double V[3][3], double w[3]) {
    for (int i = 0; i < 3; i++)
        for (int j = 0; j < 3; j++) V[i][j] = (i == j) ? 1.0 : 0.0;
    const int PQ[3][2] = {{0, 1}, {0, 2}, {1, 2}};
    for (int sweep = 0; sweep < 64; sweep++) {
        double off = A[0][1] * A[0][1] + A[0][2] * A[0][2] + A[1][2] * A[1][2];
        if (off < 1e-300) break;
        for (int r = 0; r < 3; r++) {
            int p = PQ[r][0], q = PQ[r][1];
            double apq = A[p][q];
            if (fabs(apq) < 1e-300) continue;
            double theta = (A[q][q] - A[p][p]) / (2.0 * apq);
            double tt = (theta >= 0.0 ? 1.0 : -1.0) / (fabs(theta) + sqrt(theta * theta + 1.0));
            double c = 1.0 / sqrt(tt * tt + 1.0);
            double s = tt * c;
            double app = A[p][p], aqq = A[q][q];
            A[p][p] = app - tt * apq;
            A[q][q] = aqq + tt * apq;
            A[p][q] = A[q][p] = 0.0;
            int k = 3 - p - q;
            double akp = A[k][p], akq = A[k][q];
            A[k][p] = A[p][k] = c * akp - s * akq;
            A[k][q] = A[q][k] = s * akp + c * akq;
            for (int k2 = 0; k2 < 3; k2++) {
                double vp = V[k2][p], vq = V[k2][q];
                V[k2][p] = c * vp - s * vq;
                V[k2][q] = s * vp + c * vq;
            }
        }
    }
    for (int i = 0; i < 3; i++) w[i] = A[i][i];
    for (int pass = 0; pass < 2; pass++)
        for (int i = 0; i < 2; i++)
            if (w[i] > w[i + 1]) {
                double tw = w[i]; w[i] = w[i + 1]; w[i + 1] = tw;
                for (int k = 0; k < 3; k++) {
                    double tv = V[k][i]; V[k][i] = V[k][i + 1]; V[k][i + 1] = tv;
                }
            }
}

// ---------------- finalize stats -> eigvecs, phi ranks (global, sentinel-offset) ----
__global__ void k_finalize1() {
    double n = g_acc[0];
    double mu0 = g_acc[1] / n, mu1 = g_acc[2] / n, mu2 = g_acc[3] / n;
    double inv = 1.0 / (n - 1.0);
    double A[3][3];
    A[0][0] = (g_acc[4] - n * mu0 * mu0) * inv;
    A[0][1] = A[1][0] = (g_acc[5] - n * mu0 * mu1) * inv;
    A[0][2] = A[2][0] = (g_acc[6] - n * mu0 * mu2) * inv;
    A[1][1] = (g_acc[7] - n * mu1 * mu1) * inv;
    A[1][2] = A[2][1] = (g_acc[8] - n * mu1 * mu2) * inv;
    A[2][2] = (g_acc[9] - n * mu2 * mu2) * inv;
    double V[3][3], w[3];
    eig3(A, V, w);
    for (int i = 0; i < 3; i++) {
        g_emid[i] = V[i][1];  g_elarge[i] = V[i][2];
        g_emidf[i] = (float)V[i][1]; g_elargef[i] = (float)V[i][2];
    }
    long long nrej = (long long)NP - (long long)llrint(n);
    double nm1 = n - 1.0;
    g_rank[0] = nrej + llrint(0.01 * 1.0 * nm1);    // minPhi global index
    g_rank[1] = nrej + llrint(0.01 * 99.0 * nm1);   // maxPhi global index
    g_pfx[0] = 0u; g_pfx[1] = 0u;
}

// ---------------- pass 2: phi keys for ALL pixels (sentinel 0) + fused top-byte hist
__global__ void k_phi() {
    __shared__ unsigned sh[256];
    for (int i = threadIdx.x; i < 256; i += blockDim.x) sh[i] = 0u;
    __syncthreads();
    float e10 = g_emidf[0], e11 = g_emidf[1], e12 = g_emidf[2];
    float e20 = g_elargef[0], e21 = g_elargef[1], e22 = g_elargef[2];
    int tid = blockIdx.x * blockDim.x + threadIdx.x;
    int stride = gridDim.x * blockDim.x;
    for (int q = tid; q < NP / 4; q += stride) {
        int t = q << 2;
        float4 o0 = *(const float4*)(g_od + t);
        float4 o1 = *(const float4*)(g_od + NP + t);
        float4 o2 = *(const float4*)(g_od + 2 * NP + t);
        float a0[4] = {o0.x, o0.y, o0.z, o0.w};
        float a1[4] = {o1.x, o1.y, o1.z, o1.w};
        float a2[4] = {o2.x, o2.y, o2.z, o2.w};
        unsigned keys[4];
#pragma unroll
        for (int j = 0; j < 4; j++) {
            bool keep = !(a0[j] < BETA_F || a1[j] < BETA_F || a2[j] < BETA_F);
            unsigned key = 0u;
            if (keep) {
                float t1 = fmaf(a2[j], e12, fmaf(a1[j], e11, a0[j] * e10));
                float t2 = fmaf(a2[j], e22, fmaf(a1[j], e21, a0[j] * e20));
                key = f2k(atan2f(t2, t1));
            }
            keys[j] = key;
            hadd(sh, key >> 24, true);
        }
        *(uint4*)(g_keysA + t) = make_uint4(keys[0], keys[1], keys[2], keys[3]);
    }
    __syncthreads();
    for (int i = threadIdx.x; i < 256; i += blockDim.x) {
        unsigned c = sh[i];
        if (c) { atomicAdd(&g_hist[0][i], c); atomicAdd(&g_hist[1][i], c); }
    }
}

// ---------------- radix-select histogram pass (uint4, match-aggregated) ------------
__global__ void k_hist(int shift, int useB) {
    __shared__ unsigned sh[2][256];
    for (int i = threadIdx.x; i < 512; i += blockDim.x) ((unsigned*)sh)[i] = 0u;
    __syncthreads();
    unsigned p0 = g_pfx[0], p1 = g_pfx[1];
    int tid = blockIdx.x * blockDim.x + threadIdx.x;
    int stride = gridDim.x * blockDim.x;
    for (int q = tid; q < NP / 4; q += stride) {
        int t = q << 2;
        uint4 va = *(const uint4*)(g_keysA + t);
        unsigned ka[4] = {va.x, va.y, va.z, va.w};
        if (useB) {
            uint4 vb = *(const uint4*)(g_keysB + t);
            unsigned kb[4] = {vb.x, vb.y, vb.z, vb.w};
#pragma unroll
            for (int j = 0; j < 4; j++) {
                hadd(sh[0], (ka[j] >> shift) & 255u, (ka[j] >> (shift + 8)) == p0);
                hadd(sh[1], (kb[j] >> shift) & 255u, (kb[j] >> (shift + 8)) == p1);
            }
        } else {
#pragma unroll
            for (int j = 0; j < 4; j++) {
                hadd(sh[0], (ka[j] >> shift) & 255u, (ka[j] >> (shift + 8)) == p0);
                hadd(sh[1], (ka[j] >> shift) & 255u, (ka[j] >> (shift + 8)) == p1);
            }
        }
    }
    __syncthreads();
    for (int i = threadIdx.x; i < 256; i += blockDim.x) {
        if (sh[0][i]) atomicAdd(&g_hist[0][i], sh[0][i]);
        if (sh[1][i]) atomicAdd(&g_hist[1][i], sh[1][i]);
    }
}

// ---------------- radix-select rank refine (one warp per target) ----------------
__global__ void k_select() {
    int tsel = threadIdx.x >> 5;
    int lane = threadIdx.x & 31;
    if (tsel > 1) return;
    long long r = g_rank[tsel];
    unsigned run = 0u; int found = -1; unsigned before = 0u;
    for (int base = 0; base < 256; base += 32) {
        unsigned c = g_hist[tsel][base + lane];
        unsigned inc = c;
#pragma unroll
        for (int o = 1; o < 32; o <<= 1) {
            unsigned v = __shfl_up_sync(0xffffffffu, inc, o);
            if (lane >= o) inc += v;
        }
        unsigned tot = __shfl_sync(0xffffffffu, inc, 31);
        if (found < 0) {
            long long excl = (long long)run + (long long)(inc - c);
            long long cum  = (long long)run + (long long)inc;
            bool hit = (excl <= r) && (cum > r);
            unsigned hm = __ballot_sync(0xffffffffu, hit);
            if (hm) {
                int hl = __ffs(hm) - 1;
                found = base + hl;
                before = run + __shfl_sync(0xffffffffu, inc - c, hl);
            }
        }
        run += tot;
        g_hist[tsel][base + lane] = 0u;
    }
    if (lane == 0) {
        g_pfx[tsel] = (g_pfx[tsel] << 8) | (unsigned)found;
        g_rank[tsel] = r - (long long)before;
    }
}

// ---------------- finalize phi -> HE -> M, set Cmat ranks ----------------
__global__ void k_finalize2() {
    double minPhi = (double)k2f(g_pfx[0]);
    double maxPhi = (double)k2f(g_pfx[1]);
    double vMin[3], vMax[3];
    double cmin = cos(minPhi), smin = sin(minPhi);
    double cmax = cos(maxPhi), smax = sin(maxPhi);
    for (int i = 0; i < 3; i++) {
        vMin[i] = cmin * g_emid[i] + smin * g_elarge[i];
        vMax[i] = cmax * g_emid[i] + smax * g_elarge[i];
    }
    double h1[3], h2[3];
    if (vMin[0] > vMax[0]) {
        for (int i = 0; i < 3; i++) { h1[i] = vMin[i]; h2[i] = vMax[i]; }
    } else {
        for (int i = 0; i < 3; i++) { h1[i] = vMax[i]; h2[i] = vMin[i]; }
    }
    double a = h1[0]*h1[0] + h1[1]*h1[1] + h1[2]*h1[2];
    double b = h1[0]*h2[0] + h1[1]*h2[1] + h1[2]*h2[2];
    double d = h2[0]*h2[0] + h2[1]*h2[1] + h2[2]*h2[2];
    double det = a * d - b * b;
    for (int i = 0; i < 3; i++) {
        g_M[i]     = (float)((d * h1[i] - b * h2[i]) / det);
        g_M[3 + i] = (float)((a * h2[i] - b * h1[i]) / det);
    }
    double nm1 = (double)(NP - 1);
    long long r99 = llrint(0.01 * 99.0 * nm1);
    g_rank[0] = r99; g_rank[1] = r99;
    g_pfx[0] = 0u; g_pfx[1] = 0u;
}

// ---------------- pass 3: Cmat keys for all pixels + fused top-byte hists ----------
__global__ void k_cmat() {
    __shared__ unsigned sh[2][256];
    for (int i = threadIdx.x; i < 512; i += blockDim.x) ((unsigned*)sh)[i] = 0u;
    __syncthreads();
    float m0 = g_M[0], m1 = g_M[1], m2 = g_M[2];
    float m3 = g_M[3], m4 = g_M[4], m5 = g_M[5];
    int tid = blockIdx.x * blockDim.x + threadIdx.x;
    int stride = gridDim.x * blockDim.x;
    for (int q = tid; q < NP / 4; q += stride) {
        int t = q << 2;
        float4 o0 = *(const float4*)(g_od + t);
        float4 o1 = *(const float4*)(g_od + NP + t);
        float4 o2 = *(const float4*)(g_od + 2 * NP + t);
        float a0[4] = {o0.x, o0.y, o0.z, o0.w};
        float a1[4] = {o1.x, o1.y, o1.z, o1.w};
        float a2[4] = {o2.x, o2.y, o2.z, o2.w};
        unsigned kA[4], kB[4];
#pragma unroll
        for (int j = 0; j < 4; j++) {
            float c0 = fmaf(a2[j], m2, fmaf(a1[j], m1, a0[j] * m0));
            float c1 = fmaf(a2[j], m5, fmaf(a1[j], m4, a0[j] * m3));
            kA[j] = f2k(c0); kB[j] = f2k(c1);
            hadd(sh[0], kA[j] >> 24, true);
            hadd(sh[1], kB[j] >> 24, true);
        }
        *(uint4*)(g_keysA + t) = make_uint4(kA[0], kA[1], kA[2], kA[3]);
        *(uint4*)(g_keysB + t) = make_uint4(kB[0], kB[1], kB[2], kB[3]);
    }
    __syncthreads();
    for (int i = threadIdx.x; i < 256; i += blockDim.x) {
        if (sh[0][i]) atomicAdd(&g_hist[0][i], sh[0][i]);
        if (sh[1][i]) atomicAdd(&g_hist[1][i], sh[1][i]);
    }
}

// ---------------- finalize maxC -> scales ----------------
__global__ void k_finalize3() {
    g_s[0] = 1.9705f / k2f(g_pfx[0]);
    g_s[1] = 1.0308f / k2f(g_pfx[1]);
}

// ---------------- pass 4: normalized output (FFMA-only exp) ----------------
__global__ void k_out(float* __restrict__ out) {
    float m0 = g_M[0], m1 = g_M[1], m2 = g_M[2];
    float m3 = g_M[3], m4 = g_M[4], m5 = g_M[5];
    float s0 = g_s[0], s1 = g_s[1];
    int tid = blockIdx.x * blockDim.x + threadIdx.x;
    int stride = gridDim.x * blockDim.x;
    for (int q = tid; q < NP / 4; q += stride) {
        int t = q << 2;
        float4 o0 = *(const float4*)(g_od + t);
        float4 o1 = *(const float4*)(g_od + NP + t);
        float4 o2 = *(const float4*)(g_od + 2 * NP + t);
        float a0[4] = {o0.x, o0.y, o0.z, o0.w};
        float a1[4] = {o1.x, o1.y, o1.z, o1.w};
        float a2[4] = {o2.x, o2.y, o2.z, o2.w};
        float r0[4], r1[4], r2[4];
#pragma unroll
        for (int j = 0; j < 4; j++) {
            float c0 = fmaf(a2[j], m2, fmaf(a1[j], m1, a0[j] * m0)) * s0;
            float c1 = fmaf(a2[j], m5, fmaf(a1[j], m4, a0[j] * m3)) * s1;
            r0[j] = fminf(240.0f * fexp(-fmaf(0.5626f, c0, 0.2159f * c1)), 255.0f);
            r1[j] = fminf(240.0f * fexp(-fmaf(0.7201f, c0, 0.8012f * c1)), 255.0f);
            r2[j] = fminf(240.0f * fexp(-fmaf(0.4062f, c0, 0.5581f * c1)), 255.0f);
        }
        int b = t >> 18, hw = t & (HW - 1);
        float* o = out + (size_t)b * BSTRIDE + hw;
        *(float4*)(o)          = make_float4(r0[0], r0[1], r0[2], r0[3]);
        *(float4*)(o + HW)     = make_float4(r1[0], r1[1], r1[2], r1[3]);
        *(float4*)(o + 2 * HW) = make_float4(r2[0], r2[1], r2[2], r2[3]);
    }
}

// ---------------- launch ----------------
extern "C" void kernel_launch(void* const* d_in, const int* in_sizes, int n_in,
                              void* d_out, int out_size) {
    const float* x = (const float*)d_in[0];
    float* out = (float*)d_out;
    const int TB = 256;
    const int GB = 2048;

    k_init<<<1, 256>>>();
    k_stats<<<GB, TB>>>(x);
    k_finalize1<<<1, 1>>>();
    k_phi<<<GB, TB>>>();          // fused shift-24 hist
    k_select<<<1, 64>>>();
    for (int p = 0; p < 3; p++) {
        k_hist<<<GB, TB>>>(16 - 8 * p, 0);
        k_select<<<1, 64>>>();
    }
    k_finalize2<<<1, 1>>>();
    k_cmat<<<GB, TB>>>();         // fused shift-24 hists
    k_select<<<1, 64>>>();
    for (int p = 0; p < 3; p++) {
        k_hist<<<GB, TB>>>(16 - 8 * p, 1);
        k_select<<<1, 64>>>();
    }
    k_finalize3<<<1, 1>>>();
    k_out<<<GB, TB>>>(out);
}

// round 5
// speedup vs baseline: 2.0474x; 1.1009x over previous
#include <cuda_runtime.h>
#include <math.h>

#define NP 8388608          // 32*512*512 pixels
#define HW 262144           // 512*512
#define BSTRIDE 786432      // 3*HW
#define BETA_F 0.15f
#define ODMAX 5.4810        // > -log(1/240)
#define ODNEG 0.0646        // > log(256/240)

// ---------------- device scratch (zero-initialized; every run restores invariants) ---
__device__ double   g_acc[10];             // cnt, s0..2, p00,p01,p02,p11,p12,p22
__device__ double   g_emid[3], g_elarge[3];
__device__ float    g_emidf[3], g_elargef[3];
__device__ unsigned g_pfx[2];
__device__ long long g_rank[2];
__device__ float    g_M[6];                // 2x3 row-major (HE^T HE)^-1 HE^T
__device__ float    g_s[2];                // MAXCREF / maxC
__device__ float    g_kscale[2];           // cmat key scale = 65535/R
__device__ double   g_kinv[2];             // R/65535 (recovery)
__device__ unsigned g_hist[2][256];
__device__ float    g_od[3ull * NP];       // OD cache, 3 planes (96 MB)
__device__ unsigned short g_keysA[NP];     // 16-bit keys (16.75 MB)
__device__ unsigned short g_keysB[NP];

// ---------------- helpers ----------------
// FFMA-only exp(y). Cody-Waite reduction + degree-7 Taylor.
__device__ __forceinline__ float fexp(float y) {
    float z = y * 1.4426950408889634f;
    float n = rintf(z);
    float g = fmaf(n, -0.69314575f, y);
    g = fmaf(n, -1.4286068e-6f, g);
    float r = 1.9841270e-4f;
    r = fmaf(r, g, 1.3888889e-3f);
    r = fmaf(r, g, 8.3333333e-3f);
    r = fmaf(r, g, 4.1666667e-2f);
    r = fmaf(r, g, 1.6666667e-1f);
    r = fmaf(r, g, 0.5f);
    r = fmaf(r, g, 1.0f);
    r = fmaf(r, g, 1.0f);
    int ni = (int)n;
    ni = ni < -126 ? -126 : (ni > 127 ? 127 : ni);
    float s = __int_as_float((unsigned)(ni + 127) << 23);
    return r * s;
}

// warp-aggregated shared-hist add
__device__ __forceinline__ void hadd(unsigned* row, unsigned digit, bool pred) {
    unsigned mm = __ballot_sync(0xffffffffu, pred);
    if (pred) {
        unsigned peers = __match_any_sync(mm, digit);
        int lane = threadIdx.x & 31;
        int leader = __ffs(peers) - 1;
        if (lane == leader) atomicAdd(&row[digit], (unsigned)__popc(peers));
    }
}

// ---------------- pass 1: OD cache + masked moments ----------------
__global__ void k_stats(const float* __restrict__ x) {
    float a[10];
#pragma unroll
    for (int i = 0; i < 10; i++) a[i] = 0.0f;
    int tid = blockIdx.x * blockDim.x + threadIdx.x;
    int stride = gridDim.x * blockDim.x;
    for (int q = tid; q < NP / 4; q += stride) {
        int t = q << 2;
        int b = t >> 18, hw = t & (HW - 1);
        const float* p = x + (size_t)b * BSTRIDE + hw;
        float4 v0 = *(const float4*)(p);
        float4 v1 = *(const float4*)(p + HW);
        float4 v2 = *(const float4*)(p + 2 * HW);
        float o0[4], o1[4], o2[4];
        o0[0] = -logf((v0.x + 1.0f) / 240.0f); o0[1] = -logf((v0.y + 1.0f) / 240.0f);
        o0[2] = -logf((v0.z + 1.0f) / 240.0f); o0[3] = -logf((v0.w + 1.0f) / 240.0f);
        o1[0] = -logf((v1.x + 1.0f) / 240.0f); o1[1] = -logf((v1.y + 1.0f) / 240.0f);
        o1[2] = -logf((v1.z + 1.0f) / 240.0f); o1[3] = -logf((v1.w + 1.0f) / 240.0f);
        o2[0] = -logf((v2.x + 1.0f) / 240.0f); o2[1] = -logf((v2.y + 1.0f) / 240.0f);
        o2[2] = -logf((v2.z + 1.0f) / 240.0f); o2[3] = -logf((v2.w + 1.0f) / 240.0f);
        *(float4*)(g_od + t)          = make_float4(o0[0], o0[1], o0[2], o0[3]);
        *(float4*)(g_od + NP + t)     = make_float4(o1[0], o1[1], o1[2], o1[3]);
        *(float4*)(g_od + 2 * NP + t) = make_float4(o2[0], o2[1], o2[2], o2[3]);
#pragma unroll
        for (int j = 0; j < 4; j++) {
            float d0 = o0[j], d1 = o1[j], d2 = o2[j];
            bool keep = !(d0 < BETA_F || d1 < BETA_F || d2 < BETA_F);
            if (keep) {
                a[0] += 1.0f; a[1] += d0; a[2] += d1; a[3] += d2;
                a[4] += d0 * d0; a[5] += d0 * d1; a[6] += d0 * d2;
                a[7] += d1 * d1; a[8] += d1 * d2; a[9] += d2 * d2;
            }
        }
    }
    double d[10];
#pragma unroll
    for (int i = 0; i < 10; i++) d[i] = (double)a[i];
#pragma unroll
    for (int o = 16; o; o >>= 1)
#pragma unroll
        for (int i = 0; i < 10; i++) d[i] += __shfl_down_sync(0xffffffffu, d[i], o);
    __shared__ double sh[8][10];
    int lane = threadIdx.x & 31, w = threadIdx.x >> 5;
    if (lane == 0)
        for (int i = 0; i < 10; i++) sh[w][i] = d[i];
    __syncthreads();
    if (threadIdx.x == 0) {
        for (int ww = 1; ww < (int)(blockDim.x >> 5); ww++)
            for (int i = 0; i < 10; i++) sh[0][i] += sh[ww][i];
        for (int i = 0; i < 10; i++) atomicAdd(&g_acc[i], sh[0][i]);
    }
}

// ---------------- 3x3 symmetric Jacobi eigensolver (double) ----------------
__device__ void eig3(double A[3][3], double V[3][3], double w[3]) {
    for (int i = 0; i < 3; i++)
        for (int j = 0; j < 3; j++) V[i][j] = (i == j) ? 1.0 : 0.0;
    const int PQ[3][2] = {{0, 1}, {0, 2}, {1, 2}};
    for (int sweep = 0; sweep < 64; sweep++) {
        double off = A[0][1] * A[0][1] + A[0][2] * A[0][2] + A[1][2] * A[1][2];
        if (off < 1e-300) break;
        for (int r = 0; r < 3; r++) {
            int p = PQ[r][0], q = PQ[r][1];
            double apq = A[p][q];
            if (fabs(apq) < 1e-300) continue;
            double theta = (A[q][q] - A[p][p]) / (2.0 * apq);
            double tt = (theta >= 0.0 ? 1.0 : -1.0) / (fabs(theta) + sqrt(theta * theta + 1.0));
            double c = 1.0 / sqrt(tt * tt + 1.0);
            double s = tt * c;
            double app = A[p][p], aqq = A[q][q];
            A[p][p] = app - tt * apq;
            A[q][q] = aqq + tt * apq;
            A[p][q] = A[q][p] = 0.0;
            int k = 3 - p - q;
            double akp = A[k][p], akq = A[k][q];
            A[k][p] = A[p][k] = c * akp - s * akq;
            A[k][q] = A[q][k] = s * akp + c * akq;
            for (int k2 = 0; k2 < 3; k2++) {
                double vp = V[k2][p], vq = V[k2][q];
                V[k2][p] = c * vp - s * vq;
                V[k2][q] = s * vp + c * vq;
            }
        }
    }
    for (int i = 0; i < 3; i++) w[i] = A[i][i];
    for (int pass = 0; pass < 2; pass++)
        for (int i = 0; i < 2; i++)
            if (w[i] > w[i + 1]) {
                double tw = w[i]; w[i] = w[i + 1]; w[i + 1] = tw;
                for (int k = 0; k < 3; k++) {
                    double tv = V[k][i]; V[k][i] = V[k][i + 1]; V[k][i + 1] = tv;
                }
            }
}

// ---------------- finalize stats -> eigvecs, phi ranks; restore g_acc invariant ----
__global__ void k_finalize1() {
    double n = g_acc[0];
    double mu0 = g_acc[1] / n, mu1 = g_acc[2] / n, mu2 = g_acc[3] / n;
    double inv = 1.0 / (n - 1.0);
    double A[3][3];
    A[0][0] = (g_acc[4] - n * mu0 * mu0) * inv;
    A[0][1] = A[1][0] = (g_acc[5] - n * mu0 * mu1) * inv;
    A[0][2] = A[2][0] = (g_acc[6] - n * mu0 * mu2) * inv;
    A[1][1] = (g_acc[7] - n * mu1 * mu1) * inv;
    A[1][2] = A[2][1] = (g_acc[8] - n * mu1 * mu2) * inv;
    A[2][2] = (g_acc[9] - n * mu2 * mu2) * inv;
    double V[3][3], w[3];
    eig3(A, V, w);
    for (int i = 0; i < 3; i++) {
        g_emid[i] = V[i][1];  g_elarge[i] = V[i][2];
        g_emidf[i] = (float)V[i][1]; g_elargef[i] = (float)V[i][2];
    }
    long long nrej = (long long)NP - (long long)llrint(n);
    double nm1 = n - 1.0;
    g_rank[0] = nrej + llrint(0.01 * 1.0 * nm1);
    g_rank[1] = nrej + llrint(0.01 * 99.0 * nm1);
    g_pfx[0] = 0u; g_pfx[1] = 0u;
    for (int i = 0; i < 10; i++) g_acc[i] = 0.0;   // invariant for next graph replay
}

// ---------------- pass 2: 16-bit diamond-angle keys + fused high-byte hist ---------
__global__ void k_phi() {
    __shared__ unsigned sh[256];
    for (int i = threadIdx.x; i < 256; i += blockDim.x) sh[i] = 0u;
    __syncthreads();
    float e10 = g_emidf[0], e11 = g_emidf[1], e12 = g_emidf[2];
    float e20 = g_elargef[0], e21 = g_elargef[1], e22 = g_elargef[2];
    int tid = blockIdx.x * blockDim.x + threadIdx.x;
    int stride = gridDim.x * blockDim.x;
    for (int q = tid; q < NP / 4; q += stride) {
        int t = q << 2;
        float4 o0 = *(const float4*)(g_od + t);
        float4 o1 = *(const float4*)(g_od + NP + t);
        float4 o2 = *(const float4*)(g_od + 2 * NP + t);
        float a0[4] = {o0.x, o0.y, o0.z, o0.w};
        float a1[4] = {o1.x, o1.y, o1.z, o1.w};
        float a2[4] = {o2.x, o2.y, o2.z, o2.w};
        unsigned short keys[4];
#pragma unroll
        for (int j = 0; j < 4; j++) {
            bool keep = !(a0[j] < BETA_F || a1[j] < BETA_F || a2[j] < BETA_F);
            unsigned key = 0u;
            if (keep) {
                float t1 = fmaf(a2[j], e12, fmaf(a1[j], e11, a0[j] * e10));
                float t2 = fmaf(a2[j], e22, fmaf(a1[j], e21, a0[j] * e20));
                float s = fabsf(t1) + fabsf(t2);
                float p = copysignf(1.0f - __fdividef(t1, s), t2);  // diamond angle, monotone in atan2(t2,t1)
                float kf = fmaf(p, 16383.75f, 32767.5f);            // (p+2)*16383.75
                kf = fminf(fmaxf(kf, 0.0f), 65535.0f);
                key = (unsigned)kf;
            }
            keys[j] = (unsigned short)key;
            hadd(sh, key >> 8, true);
        }
        *(ushort4*)(g_keysA + t) = make_ushort4(keys[0], keys[1], keys[2], keys[3]);
    }
    __syncthreads();
    for (int i = threadIdx.x; i < 256; i += blockDim.x) {
        unsigned c = sh[i];
        if (c) { atomicAdd(&g_hist[0][i], c); atomicAdd(&g_hist[1][i], c); }
    }
}

// ---------------- low-byte histogram pass over 16-bit keys ----------------
__global__ void k_hist2(int useB) {
    __shared__ unsigned sh[2][256];
    for (int i = threadIdx.x; i < 512; i += blockDim.x) ((unsigned*)sh)[i] = 0u;
    __syncthreads();
    unsigned p0 = g_pfx[0], p1 = g_pfx[1];
    int tid = blockIdx.x * blockDim.x + threadIdx.x;
    int stride = gridDim.x * blockDim.x;
    for (int q = tid; q < NP / 8; q += stride) {
        uint4 va = ((const uint4*)g_keysA)[q];
        unsigned ka[8] = {va.x & 0xFFFFu, va.x >> 16, va.y & 0xFFFFu, va.y >> 16,
                          va.z & 0xFFFFu, va.z >> 16, va.w & 0xFFFFu, va.w >> 16};
        if (useB) {
            uint4 vb = ((const uint4*)g_keysB)[q];
            unsigned kb[8] = {vb.x & 0xFFFFu, vb.x >> 16, vb.y & 0xFFFFu, vb.y >> 16,
                              vb.z & 0xFFFFu, vb.z >> 16, vb.w & 0xFFFFu, vb.w >> 16};
#pragma unroll
            for (int j = 0; j < 8; j++) {
                hadd(sh[0], ka[j] & 255u, (ka[j] >> 8) == p0);
                hadd(sh[1], kb[j] & 255u, (kb[j] >> 8) == p1);
            }
        } else {
#pragma unroll
            for (int j = 0; j < 8; j++) {
                hadd(sh[0], ka[j] & 255u, (ka[j] >> 8) == p0);
                hadd(sh[1], ka[j] & 255u, (ka[j] >> 8) == p1);
            }
        }
    }
    __syncthreads();
    for (int i = threadIdx.x; i < 256; i += blockDim.x) {
        if (sh[0][i]) atomicAdd(&g_hist[0][i], sh[0][i]);
        if (sh[1][i]) atomicAdd(&g_hist[1][i], sh[1][i]);
    }
}

// ---------------- select + staged finalize ----------------
// stage 0: plain digit select. stage 1: + phi->HE->M finalize. stage 2: + maxC scales.
__global__ void k_select(int stage) {
    int tsel = threadIdx.x >> 5;         // launched with 64 threads: tsel in {0,1}
    int lane = threadIdx.x & 31;
    long long r = g_rank[tsel];
    unsigned run = 0u; int found = -1; unsigned before = 0u;
    for (int base = 0; base < 256; base += 32) {
        unsigned c = g_hist[tsel][base + lane];
        unsigned inc = c;
#pragma unroll
        for (int o = 1; o < 32; o <<= 1) {
            unsigned v = __shfl_up_sync(0xffffffffu, inc, o);
            if (lane >= o) inc += v;
        }
        unsigned tot = __shfl_sync(0xffffffffu, inc, 31);
        if (found < 0) {
            long long excl = (long long)run + (long long)(inc - c);
            long long cum  = (long long)run + (long long)inc;
            bool hit = (excl <= r) && (cum > r);
            unsigned hm = __ballot_sync(0xffffffffu, hit);
            if (hm) {
                int hl = __ffs(hm) - 1;
                found = base + hl;
                before = run + __shfl_sync(0xffffffffu, inc - c, hl);
            }
        }
        run += tot;
        g_hist[tsel][base + lane] = 0u;   // restore invariant
    }
    if (lane == 0) {
        g_pfx[tsel] = (g_pfx[tsel] << 8) | (unsigned)found;
        g_rank[tsel] = r - (long long)before;
    }
    __syncthreads();
    if (threadIdx.x == 0) {
        if (stage == 1) {
            // --- finalize phi -> HE -> M, cmat key scales, cmat ranks ---
            double ph[2];
            for (int t = 0; t < 2; t++) {
                double p = ((double)g_pfx[t] + 0.5) / 16383.75 - 2.0;   // bin center
                double ap = fabs(p);
                double xx = 1.0 - ap;
                double yy = (1.0 - fabs(1.0 - ap)); yy = (p < 0.0) ? -yy : yy;
                ph[t] = atan2(yy, xx);
            }
            double minPhi = ph[0], maxPhi = ph[1];
            double vMin[3], vMax[3];
            double cmin = cos(minPhi), smin = sin(minPhi);
            double cmax = cos(maxPhi), smax = sin(maxPhi);
            for (int i = 0; i < 3; i++) {
                vMin[i] = cmin * g_emid[i] + smin * g_elarge[i];
                vMax[i] = cmax * g_emid[i] + smax * g_elarge[i];
            }
            double h1[3], h2[3];
            if (vMin[0] > vMax[0]) {
                for (int i = 0; i < 3; i++) { h1[i] = vMin[i]; h2[i] = vMax[i]; }
            } else {
                for (int i = 0; i < 3; i++) { h1[i] = vMax[i]; h2[i] = vMin[i]; }
            }
            double a = h1[0]*h1[0] + h1[1]*h1[1] + h1[2]*h1[2];
            double b = h1[0]*h2[0] + h1[1]*h2[1] + h1[2]*h2[2];
            double d = h2[0]*h2[0] + h2[1]*h2[1] + h2[2]*h2[2];
            double det = a * d - b * b;
            double M[6];
            for (int i = 0; i < 3; i++) {
                M[i]     = (d * h1[i] - b * h2[i]) / det;
                M[3 + i] = (a * h2[i] - b * h1[i]) / det;
            }
            for (int i = 0; i < 6; i++) g_M[i] = (float)M[i];
            // upper bound R per row: max of M.od over od_i in [-ODNEG, ODMAX]
            for (int t = 0; t < 2; t++) {
                double R = 0.0;
                for (int i = 0; i < 3; i++) {
                    double m = M[3 * t + i];
                    R += (m > 0.0) ? m * ODMAX : -m * ODNEG;
                }
                R = R * 1.001 + 1e-6;
                g_kscale[t] = (float)(65535.0 / R);
                g_kinv[t] = R / 65535.0;
            }
            long long r99 = llrint(0.01 * 99.0 * (double)(NP - 1));
            g_rank[0] = r99; g_rank[1] = r99;
            g_pfx[0] = 0u; g_pfx[1] = 0u;
        } else if (stage == 2) {
            g_s[0] = (float)(1.9705 / (((double)g_pfx[0] + 0.5) * g_kinv[0]));
            g_s[1] = (float)(1.0308 / (((double)g_pfx[1] + 0.5) * g_kinv[1]));
        }
    }
}

// ---------------- pass 3: 16-bit Cmat keys + fused high-byte hists ----------------
__global__ void k_cmat() {
    __shared__ unsigned sh[2][256];
    for (int i = threadIdx.x; i < 512; i += blockDim.x) ((unsigned*)sh)[i] = 0u;
    __syncthreads();
    float m0 = g_M[0], m1 = g_M[1], m2 = g_M[2];
    float m3 = g_M[3], m4 = g_M[4], m5 = g_M[5];
    float s0 = g_kscale[0], s1 = g_kscale[1];
    int tid = blockIdx.x * blockDim.x + threadIdx.x;
    int stride = gridDim.x * blockDim.x;
    for (int q = tid; q < NP / 4; q += stride) {
        int t = q << 2;
        float4 o0 = *(const float4*)(g_od + t);
        float4 o1 = *(const float4*)(g_od + NP + t);
        float4 o2 = *(const float4*)(g_od + 2 * NP + t);
        float a0[4] = {o0.x, o0.y, o0.z, o0.w};
        float a1[4] = {o1.x, o1.y, o1.z, o1.w};
        float a2[4] = {o2.x, o2.y, o2.z, o2.w};
        unsigned short kA[4], kB[4];
#pragma unroll
        for (int j = 0; j < 4; j++) {
            float c0 = fmaf(a2[j], m2, fmaf(a1[j], m1, a0[j] * m0));
            float c1 = fmaf(a2[j], m5, fmaf(a1[j], m4, a0[j] * m3));
            float f0 = fminf(fmaxf(c0 * s0, 0.0f), 65535.0f);
            float f1 = fminf(fmaxf(c1 * s1, 0.0f), 65535.0f);
            unsigned u0 = (unsigned)f0, u1 = (unsigned)f1;
            kA[j] = (unsigned short)u0; kB[j] = (unsigned short)u1;
            hadd(sh[0], u0 >> 8, true);
            hadd(sh[1], u1 >> 8, true);
        }
        *(ushort4*)(g_keysA + t) = make_ushort4(kA[0], kA[1], kA[2], kA[3]);
        *(ushort4*)(g_keysB + t) = make_ushort4(kB[0], kB[1], kB[2], kB[3]);
    }
    __syncthreads();
    for (int i = threadIdx.x; i < 256; i += blockDim.x) {
        if (sh[0][i]) atomicAdd(&g_hist[0][i], sh[0][i]);
        if (sh[1][i]) atomicAdd(&g_hist[1][i], sh[1][i]);
    }
}

// ---------------- pass 4: normalized output (FFMA-only exp) ----------------
__global__ void k_out(float* __restrict__ out) {
    float m0 = g_M[0], m1 = g_M[1], m2 = g_M[2];
    float m3 = g_M[3], m4 = g_M[4], m5 = g_M[5];
    float s0 = g_s[0], s1 = g_s[1];
    int tid = blockIdx.x * blockDim.x + threadIdx.x;
    int stride = gridDim.x * blockDim.x;
    for (int q = tid; q < NP / 4; q += stride) {
        int t = q << 2;
        float4 o0 = *(const float4*)(g_od + t);
        float4 o1 = *(const float4*)(g_od + NP + t);
        float4 o2 = *(const float4*)(g_od + 2 * NP + t);
        float a0[4] = {o0.x, o0.y, o0.z, o0.w};
        float a1[4] = {o1.x, o1.y, o1.z, o1.w};
        float a2[4] = {o2.x, o2.y, o2.z, o2.w};
        float r0[4], r1[4], r2[4];
#pragma unroll
        for (int j = 0; j < 4; j++) {
            float c0 = fmaf(a2[j], m2, fmaf(a1[j], m1, a0[j] * m0)) * s0;
            float c1 = fmaf(a2[j], m5, fmaf(a1[j], m4, a0[j] * m3)) * s1;
            r0[j] = fminf(240.0f * fexp(-fmaf(0.5626f, c0, 0.2159f * c1)), 255.0f);
            r1[j] = fminf(240.0f * fexp(-fmaf(0.7201f, c0, 0.8012f * c1)), 255.0f);
            r2[j] = fminf(240.0f * fexp(-fmaf(0.4062f, c0, 0.5581f * c1)), 255.0f);
        }
        int b = t >> 18, hw = t & (HW - 1);
        float* o = out + (size_t)b * BSTRIDE + hw;
        *(float4*)(o)          = make_float4(r0[0], r0[1], r0[2], r0[3]);
        *(float4*)(o + HW)     = make_float4(r1[0], r1[1], r1[2], r1[3]);
        *(float4*)(o + 2 * HW) = make_float4(r2[0], r2[1], r2[2], r2[3]);
    }
}

// ---------------- launch (11 kernels) ----------------
extern "C" void kernel_launch(void* const* d_in, const int* in_sizes, int n_in,
                              void* d_out, int out_size) {
    const float* x = (const float*)d_in[0];
    float* out = (float*)d_out;
    const int TB = 256;
    const int GB = 2048;

    k_stats<<<GB, TB>>>(x);
    k_finalize1<<<1, 1>>>();
    k_phi<<<GB, TB>>>();             // keys + fused high-byte hist
    k_select<<<1, 64>>>(0);
    k_hist2<<<GB, TB>>>(0);          // low byte
    k_select<<<1, 64>>>(1);          // select + finalize2 (HE, M, key scales)
    k_cmat<<<GB, TB>>>();            // keys + fused high-byte hists
    k_select<<<1, 64>>>(0);
    k_hist2<<<GB, TB>>>(1);          // low byte
    k_select<<<1, 64>>>(2);          // select + finalize3 (scales)
    k_out<<<GB, TB>>>(out);
}